// round 6
// baseline (speedup 1.0000x reference)
#include <cuda_runtime.h>
#include <math.h>

#define LNUM   102
#define LSTART 100               // start label = L-2
#define LPAD   104
#define NT     128
#define MAXB   1024
#define RINGW  128               // ring row width (padded so tid<128 reads are safe)

__device__ int g_perm[MAXB];
typedef unsigned long long ull;

// ---------- packed f32x2 helpers ----------
__device__ __forceinline__ void fma2(ull& d, ull a, ull b) {
    asm("fma.rn.f32x2 %0, %1, %2, %0;" : "+l"(d) : "l"(a), "l"(b));
}
__device__ __forceinline__ ull add2(ull a, ull b) {
    ull r; asm("add.rn.f32x2 %0, %1, %2;" : "=l"(r) : "l"(a), "l"(b)); return r;
}
__device__ __forceinline__ float2 unpack2(ull u) {
    float2 f; asm("mov.b64 {%0, %1}, %2;" : "=f"(f.x), "=f"(f.y) : "l"(u)); return f;
}
__device__ __forceinline__ ull pack2(float x, float y) {
    ull u; asm("mov.b64 %0, {%1, %2};" : "=l"(u) : "f"(x), "f"(y)); return u;
}

__device__ __forceinline__ void cp_async4(void* smem_dst, const void* gmem_src) {
    unsigned s;
    asm("{ .reg .u64 t; cvta.to.shared.u64 t, %1; cvt.u32.u64 %0, t; }"
        : "=r"(s) : "l"(smem_dst));
    asm volatile("cp.async.ca.shared.global [%0], [%1], 4;" :: "r"(s), "l"(gmem_src));
}

// ---------- LPT pre-sort: order batches by descending length ----------
__global__ void sort_kernel(const int* __restrict__ lens, int B) {
    __shared__ int keys[MAXB];
    const int tid = threadIdx.x;
    for (int i = tid; i < MAXB; i += blockDim.x)
        keys[i] = (i < B) ? ((lens[i] << 10) | (MAXB - 1 - i)) : -1;
    __syncthreads();
    for (int k = 2; k <= MAXB; k <<= 1) {
        for (int j = k >> 1; j > 0; j >>= 1) {
            for (int i = tid; i < MAXB; i += blockDim.x) {
                int ixj = i ^ j;
                if (ixj > i) {
                    int a = keys[i], c = keys[ixj];
                    bool seg = ((i & k) == 0);   // descending
                    if (seg ? (a < c) : (a > c)) { keys[i] = c; keys[ixj] = a; }
                }
            }
            __syncthreads();
        }
    }
    for (int i = tid; i < B; i += blockDim.x)
        g_perm[i] = (MAXB - 1) - (keys[i] & (MAXB - 1));
}

// ---------- CRF forward: linear domain, cp.async logit ring, 4 blocks/SM ----------
__global__ __launch_bounds__(NT, 4)
void crf_fwd_kernel(const float* __restrict__ logits,
                    const float* __restrict__ trans,
                    const int*   __restrict__ lens,
                    float* __restrict__ out,
                    int T)
{
    const int j    = threadIdx.x;
    const int lane = j & 31;
    const int warp = j >> 5;
    const int b    = g_perm[blockIdx.x];

    __shared__ __align__(16) float q_sh[2][LPAD];
    __shared__ float lring[4][RINGW];
    __shared__ float red[4];

    // E2[m] = exp(trans[j, 2m..2m+1]) — 52 packed pairs (pads = 0)
    ull E2[52];
    #pragma unroll
    for (int m = 0; m < 52; ++m) {
        float a = 0.f, c = 0.f;
        if (j < LNUM) {
            const float* tr = trans + (size_t)j * LNUM;
            const int k = 2 * m;
            if (k + 0 < LNUM) a = __expf(tr[k + 0]);
            if (k + 1 < LNUM) c = __expf(tr[k + 1]);
        }
        E2[m] = pack2(a, c);
    }

    // init q = exp(alpha0); zero ring (pads must read 0 -> el=1, harmless)
    if (j < LPAD) { q_sh[0][j] = (j == LSTART) ? 1.f : 0.f; q_sh[1][j] = 0.f; }
    #pragma unroll
    for (int r = 0; r < 4; ++r) lring[r][j] = 0.f;

    int len = lens[b];
    if (len > T) len = T;
    const float* lgcol = logits + (size_t)b * T * LNUM + j;

    // prime the ring: steps 0..2 (one commit group per step)
    #pragma unroll
    for (int p = 0; p < 3; ++p) {
        if (p < len && j < LNUM) cp_async4(&lring[p][j], lgcol + (size_t)p * LNUM);
        asm volatile("cp.async.commit_group;");
    }

    float C = 0.f;
    float q = (j == LSTART) ? 1.f : 0.f;

    __syncthreads();   // q_sh + ring zeros visible

    for (int t = 0; t < len; ++t) {
        // prefetch step t+3 into ring slot (t+3)&3  (distinct from slot t&3)
        const int tp = t + 3;
        if (tp < len && j < LNUM)
            cp_async4(&lring[tp & 3][j], lgcol + (size_t)tp * LNUM);
        asm volatile("cp.async.commit_group;");
        // allow 2 newest groups in flight -> group for step t (and t+1) complete
        asm volatile("cp.async.wait_group 2;");

        const float el = __expf(lring[t & 3][j]);   // self-produced slot only

        // y[j] = sum_k E[j,k] * q[k]; every 4th step fold a redundant block-max
        // (identical on all threads -> uniform renorm, no communication)
        ull a0 = 0ull, a1 = 0ull, a2 = 0ull, a3 = 0ull;
        float m0 = 0.f, m1 = 0.f;
        const bool do_max = ((t & 3) == 0);
        const ulonglong2* ps = reinterpret_cast<const ulonglong2*>(q_sh[t & 1]);
        #pragma unroll
        for (int m = 0; m < 26; ++m) {              // 26 LDS.128
            ulonglong2 v = ps[m];
            if (m & 1) { fma2(a2, E2[2 * m], v.x); fma2(a3, E2[2 * m + 1], v.y); }
            else       { fma2(a0, E2[2 * m], v.x); fma2(a1, E2[2 * m + 1], v.y); }
            if (do_max) {
                float2 fx = unpack2(v.x), fy = unpack2(v.y);
                m0 = fmaxf(m0, fmaxf(fx.x, fx.y));
                m1 = fmaxf(m1, fmaxf(fy.x, fy.y));
            }
        }
        float2 fs = unpack2(add2(add2(a0, a1), add2(a2, a3)));
        float y = fs.x + fs.y;

        if (do_max && t > 0) {                      // uniform renormalization
            const float M = fmaxf(fmaxf(m0, m1), 1e-30f);
            y *= __fdividef(1.f, M);
            C += __logf(M);
        }

        q = el * y;                                 // pads: E2=0 -> y=0 -> q=0
        if (j < LPAD) q_sh[(t + 1) & 1][j] = q;
        __syncthreads();                            // single barrier per step
    }

    // out[b] = C + log( sum_j q[j] * exp(trans[stop, j]) )
    float v = (j < LNUM)
        ? q * __expf(trans[(size_t)(LNUM - 1) * LNUM + j]) : 0.f;
    #pragma unroll
    for (int o = 16; o; o >>= 1)
        v += __shfl_xor_sync(0xffffffffu, v, o);
    if (lane == 0) red[warp] = v;
    __syncthreads();
    if (j == 0) {
        float s = (red[0] + red[1]) + (red[2] + red[3]);
        out[b] = C + logf(s);
    }
}

extern "C" void kernel_launch(void* const* d_in, const int* in_sizes, int n_in,
                              void* d_out, int out_size)
{
    const float* logits = (const float*)d_in[0];   // [B, T, L] f32
    const float* trans  = (const float*)d_in[1];   // [L, L]    f32
    const int*   lens   = (const int*)d_in[2];     // [B]       i32
    float*       out    = (float*)d_out;           // [B]       f32

    const int B = in_sizes[2];
    const int T = in_sizes[0] / (B * LNUM);

    sort_kernel<<<1, MAXB>>>(lens, B);
    crf_fwd_kernel<<<B, NT>>>(logits, trans, lens, out, T);
}

// round 7
// speedup vs baseline: 1.8803x; 1.8803x over previous
#include <cuda_runtime.h>
#include <math.h>

#define LNUM   102
#define LSTART 100               // start label = L-2
#define LPAD   104
#define NT     128
#define MAXB   1024
#define SCALE  4.0f              // constant per-step rescale (nats), folded into exp

__device__ int g_perm[MAXB];
typedef unsigned long long ull;

// ---------- packed f32x2 helpers ----------
__device__ __forceinline__ void fma2(ull& d, ull a, ull b) {
    asm("fma.rn.f32x2 %0, %1, %2, %0;" : "+l"(d) : "l"(a), "l"(b));
}
__device__ __forceinline__ ull mul2(ull a, ull b) {
    ull r; asm("mul.rn.f32x2 %0, %1, %2;" : "=l"(r) : "l"(a), "l"(b)); return r;
}
__device__ __forceinline__ ull add2(ull a, ull b) {
    ull r; asm("add.rn.f32x2 %0, %1, %2;" : "=l"(r) : "l"(a), "l"(b)); return r;
}
__device__ __forceinline__ float2 unpack2(ull u) {
    float2 f; asm("mov.b64 {%0, %1}, %2;" : "=f"(f.x), "=f"(f.y) : "l"(u)); return f;
}
__device__ __forceinline__ ull pack2(float x, float y) {
    ull u; asm("mov.b64 %0, {%1, %2};" : "=l"(u) : "f"(x), "f"(y)); return u;
}

// ---------- LPT pre-sort: order batches by descending length ----------
__global__ void sort_kernel(const int* __restrict__ lens, int B) {
    __shared__ int keys[MAXB];
    const int tid = threadIdx.x;
    for (int i = tid; i < MAXB; i += blockDim.x)
        keys[i] = (i < B) ? ((lens[i] << 10) | (MAXB - 1 - i)) : -1;
    __syncthreads();
    for (int k = 2; k <= MAXB; k <<= 1) {
        for (int j = k >> 1; j > 0; j >>= 1) {
            for (int i = tid; i < MAXB; i += blockDim.x) {
                int ixj = i ^ j;
                if (ixj > i) {
                    int a = keys[i], c = keys[ixj];
                    bool seg = ((i & k) == 0);   // descending
                    if (seg ? (a < c) : (a > c)) { keys[i] = c; keys[ixj] = a; }
                }
            }
            __syncthreads();
        }
    }
    for (int i = tid; i < B; i += blockDim.x)
        g_perm[i] = (MAXB - 1) - (keys[i] & (MAXB - 1));
}

// ---------- CRF forward: linear domain, constant scale + 16-step exact renorm ----------
__global__ __launch_bounds__(NT, 3)
void crf_fwd_kernel(const float* __restrict__ logits,
                    const float* __restrict__ trans,
                    const int*   __restrict__ lens,
                    float* __restrict__ out,
                    int T)
{
    const int j    = threadIdx.x;
    const int lane = j & 31;
    const int warp = j >> 5;
    const int b    = g_perm[blockIdx.x];

    __shared__ __align__(16) float q_sh[2][LPAD];
    __shared__ float red[4];

    // E2[m] = exp(trans[j, 2m .. 2m+1]) — 52 packed f32x2 pairs (pads = 0)
    ull E2[52];
    #pragma unroll
    for (int m = 0; m < 52; ++m) {
        float a = 0.f, c = 0.f;
        if (j < LNUM) {
            const float* tr = trans + (size_t)j * LNUM;
            const int k = 2 * m;
            if (k + 0 < LNUM) a = __expf(tr[k + 0]);
            if (k + 1 < LNUM) c = __expf(tr[k + 1]);
        }
        E2[m] = pack2(a, c);
    }

    // init q = exp(alpha0): 1 at start label, 0 elsewhere
    float q = (j == LSTART) ? 1.f : 0.f;
    if (j < LPAD) { q_sh[0][j] = q; q_sh[1][j] = 0.f; }

    int len = lens[b];
    if (len > T) len = T;
    const float* lg = logits + (size_t)b * T * LNUM;

    float C = 0.f;       // accumulated exact-renorm log scales

    // depth-4 register logit pipeline (proven in R4)
    float lgq[4];
    #pragma unroll
    for (int u = 0; u < 4; ++u)
        lgq[u] = (u < len && j < LNUM) ? lg[(size_t)u * LNUM + j] : 0.f;

    __syncthreads();

    for (int tc = 0; tc < len; tc += 4) {
        // prefetch next chunk's logits: 4 independent LDGs (MLP=4)
        float lgn[4];
        #pragma unroll
        for (int u = 0; u < 4; ++u) {
            const int tl = tc + 4 + u;
            lgn[u] = (tl < len && j < LNUM) ? lg[(size_t)tl * LNUM + j] : 0.f;
        }

        #pragma unroll
        for (int u = 0; u < 4; ++u) {
            const int t = tc + u;
            if (t >= len) break;                    // uniform across block

            // constant per-step rescale folded into the exp (zero extra cost)
            const float el = __expf(lgq[u] - SCALE);

            // exact (redundant, communication-free) renorm only every 16 steps
            const bool do_max = ((t & 15) == 0) && (tc + u > 0) && (u == 0);

            // y[j] = sum_k E[j,k] * q[k] — 26 LDS.128 broadcast + 52 FMA2
            const ulonglong2* ps =
                reinterpret_cast<const ulonglong2*>(q_sh[t & 1]);
            ulonglong2 v0 = ps[0];
            ulonglong2 v1 = ps[1];
            ull a0 = mul2(E2[0], v0.x);
            ull a1 = mul2(E2[1], v0.y);
            ull a2 = mul2(E2[2], v1.x);
            ull a3 = mul2(E2[3], v1.y);
            float m0 = 0.f, m1 = 0.f;
            if (do_max) {
                float2 fx = unpack2(v0.x), fy = unpack2(v0.y);
                float2 gx = unpack2(v1.x), gy = unpack2(v1.y);
                m0 = fmaxf(fmaxf(fx.x, fx.y), fmaxf(gx.x, gx.y));
                m1 = fmaxf(fmaxf(fy.x, fy.y), fmaxf(gy.x, gy.y));
            }
            #pragma unroll
            for (int m = 2; m < 26; ++m) {
                ulonglong2 v = ps[m];
                if (m & 1) { fma2(a2, E2[2 * m], v.x); fma2(a3, E2[2 * m + 1], v.y); }
                else       { fma2(a0, E2[2 * m], v.x); fma2(a1, E2[2 * m + 1], v.y); }
                if (do_max) {
                    float2 fx = unpack2(v.x), fy = unpack2(v.y);
                    m0 = fmaxf(m0, fmaxf(fx.x, fx.y));
                    m1 = fmaxf(m1, fmaxf(fy.x, fy.y));
                }
            }
            float2 fs = unpack2(add2(add2(a0, a1), add2(a2, a3)));
            float y = fs.x + fs.y;

            if (do_max) {                           // uniform, identical on all threads
                const float M = fmaxf(fmaxf(m0, m1), 1e-30f);
                y *= __fdividef(1.f, M);
                C += __logf(M);
            }

            q = el * y;                             // pads: E2=0 -> y=0 -> q=0
            if (j < LPAD) q_sh[(t + 1) & 1][j] = q;
            __syncthreads();                        // single barrier per step
        }

        #pragma unroll
        for (int u = 0; u < 4; ++u) lgq[u] = lgn[u];
    }

    // out[b] = C + SCALE*len + log( sum_j q[j] * exp(trans[stop, j]) )
    float v = (j < LNUM)
        ? q * __expf(trans[(size_t)(LNUM - 1) * LNUM + j]) : 0.f;
    #pragma unroll
    for (int o = 16; o; o >>= 1)
        v += __shfl_xor_sync(0xffffffffu, v, o);
    if (lane == 0) red[warp] = v;
    __syncthreads();
    if (j == 0) {
        float s = (red[0] + red[1]) + (red[2] + red[3]);
        out[b] = C + SCALE * (float)len + logf(s);
    }
}

extern "C" void kernel_launch(void* const* d_in, const int* in_sizes, int n_in,
                              void* d_out, int out_size)
{
    const float* logits = (const float*)d_in[0];   // [B, T, L] f32
    const float* trans  = (const float*)d_in[1];   // [L, L]    f32
    const int*   lens   = (const int*)d_in[2];     // [B]       i32
    float*       out    = (float*)d_out;           // [B]       f32

    const int B = in_sizes[2];
    const int T = in_sizes[0] / (B * LNUM);

    sort_kernel<<<1, MAXB>>>(lens, B);
    crf_fwd_kernel<<<B, NT>>>(logits, trans, lens, out, T);
}